// round 13
// baseline (speedup 1.0000x reference)
#include <cuda_runtime.h>
#include <cuda_bf16.h>
#include <cstdint>

// ---------------------------------------------------------------------------
//   x [32,256,32,32] f32, weight [256,256,3,3] f32, gamma/beta [1024] f32
//   out [32,256,32,32] f32
//
// Dual-pipe binary-weight conv:
//   co 0..111  : bf16 m16n8k16 mma.sync, hi/lo 2-pass split (tensor pipe)
//   co 112..255: exact fp32 single pass, w = +-1, packed f32x2 FFMA (fma pipe)
// Both compute S = sum(+-x); alpha folded into BN scale in k_stats.
// Near-threshold decisions flagged in k_out, exact double recompute in k_fix.
// ---------------------------------------------------------------------------

#define TAU   0.01f
#define CAP   1048576

static __device__ uint32_t           g_wBm[4 * 9 * 32 * 112];      // bf16x2 +-1, [g][tap][kp][co<112]
static __device__ unsigned long long g_wBf[4 * 9 * 64 * 16 * 10];  // dup f32x2 +-1, [g][tap][ci][ct][10]
static __device__ float    g_alpha[256];
static __device__ float    g_psum[33554432];          // [b][g*256+co][h][w]  (holds S)
static __device__ float    g_scale[1024];
static __device__ float    g_bias[1024];
static __device__ int      g_cnt;
static __device__ int      g_list[CAP];

// ---- packed fp32x2 helpers ----
__device__ __forceinline__ unsigned long long ffma2(unsigned long long a,
                                                    unsigned long long b,
                                                    unsigned long long c) {
    unsigned long long d;
    asm("fma.rn.f32x2 %0, %1, %2, %3;" : "=l"(d) : "l"(a), "l"(b), "l"(c));
    return d;
}
__device__ __forceinline__ unsigned long long packab(float a, float b) {
    unsigned long long d;
    asm("mov.b64 %0, {%1, %2};" : "=l"(d) : "f"(a), "f"(b));
    return d;
}

// ---------------------------------------------------------------------------
// K0: alpha, weight packs (bf16x2 for MMA cos, dup-f32x2 +-1 for FFMA cos).
// ---------------------------------------------------------------------------
__global__ void k_prep(const float* __restrict__ w) {
    const int co = blockIdx.x;
    const int t  = threadIdx.x;          // 256
    if (co == 0 && t == 0) g_cnt = 0;
    __shared__ float red[256];
    const float* wc = w + co * 2304;
    float s = 0.0f;
    for (int i = t; i < 2304; i += 256) s += fabsf(wc[i]);
    red[t] = s;
    __syncthreads();
    for (int off = 128; off; off >>= 1) {
        if (t < off) red[t] += red[t + off];
        __syncthreads();
    }
    if (t == 0) g_alpha[co] = red[0] * (1.0f / 2304.0f);
    for (int i = t; i < 2304; i += 256) {
        const int ci  = i / 9;
        const int tap = i - ci * 9;
        const int g   = ci >> 6;
        const int cig = ci & 63;
        const bool pos = (wc[i] >= 0.0f);
        if (co < 112) {
            uint16_t* p = reinterpret_cast<uint16_t*>(g_wBm);
            p[((((size_t)(g * 9 + tap) * 32) + (cig >> 1)) * 112 + co) * 2 + (cig & 1)] =
                pos ? 0x3F80u : 0xBF80u;
        } else {
            const int cf = co - 112;
            const int ct = cf / 9;
            const int j  = cf - ct * 9;
            g_wBf[(((size_t)(g * 9 + tap) * 64 + cig) * 16 + ct) * 10 + j] =
                pos ? 0x3F8000003F800000ull : 0xBF800000BF800000ull;
        }
    }
}

// ---------------------------------------------------------------------------
// K1: dual-pipe conv. CTA = 128 px x 256 co for (b, g, rowTile). 512 threads.
// warps 0-7 : MMA  (4M x 2N, 32px x 56co each)  -> co 0..111
// warps 8-15: FFMA (thread = 8px x 9co)         -> co 112..255
// smem floats:
//   XF32[0,13824)  XHI[13824,20736)  XLO[20736,27648)
//   BM  [27648,31488)  (u32, [32kp][120pad])
//   BF  [31488,51968)  (u64 view, [64ci][16ct][10])
// ---------------------------------------------------------------------------
#define SM_XF32 0
#define SM_XHI  13824
#define SM_XLO  20736
#define SM_BM   27648
#define SM_BF   31488
#define SM_WORDS 51968
#define SM_BYTES (SM_WORDS * 4)

__device__ __forceinline__ void mma_bf16(float& d0, float& d1, float& d2, float& d3,
                                         uint32_t a0, uint32_t a1, uint32_t a2, uint32_t a3,
                                         uint32_t b0, uint32_t b1) {
    asm volatile(
        "mma.sync.aligned.m16n8k16.row.col.f32.bf16.bf16.f32 "
        "{%0,%1,%2,%3}, {%4,%5,%6,%7}, {%8,%9}, {%0,%1,%2,%3};"
        : "+f"(d0), "+f"(d1), "+f"(d2), "+f"(d3)
        : "r"(a0), "r"(a1), "r"(a2), "r"(a3), "r"(b0), "r"(b1));
}

__global__ void __launch_bounds__(512, 1)
k_conv(const float* __restrict__ x) {
    extern __shared__ float sm[];
    uint32_t* smu = reinterpret_cast<uint32_t*>(sm);
    unsigned long long* smw = reinterpret_cast<unsigned long long*>(sm + SM_BF);

    const int tid  = threadIdx.x;
    const int wid  = tid >> 5;
    const int lane = tid & 31;
    const int b  = blockIdx.z;
    const int g  = blockIdx.y;
    const int pt = blockIdx.x;      // 0..7
    const int r0 = pt * 4;

    // ---- stage x: fp32 slab + hi/lo bf16 slabs, ci pairs ----
    const float* xg = x + (size_t)(b * 256 + g * 64) * 1024;
    for (int i = tid; i < 6912; i += 512) {
        const int cp  = i / 216;
        const int rem = i - cp * 216;
        const int lrr = rem / 36;
        const int lc  = rem - lrr * 36;
        const int gr  = r0 - 1 + lrr;
        const int gc  = lc - 1;
        float v0 = 0.0f, v1 = 0.0f;
        if ((unsigned)gr < 32u && (unsigned)gc < 32u) {
            v0 = xg[(2 * cp) * 1024 + gr * 32 + gc];
            v1 = xg[(2 * cp + 1) * 1024 + gr * 32 + gc];
        }
        sm[SM_XF32 + (2 * cp) * 216 + rem]     = v0;
        sm[SM_XF32 + (2 * cp + 1) * 216 + rem] = v1;
        const __nv_bfloat16 h0 = __float2bfloat16_rn(v0);
        const __nv_bfloat16 h1 = __float2bfloat16_rn(v1);
        smu[SM_XHI + i] = (uint32_t)__bfloat16_as_ushort(h0) |
                          ((uint32_t)__bfloat16_as_ushort(h1) << 16);
        const float l0 = v0 - __bfloat162float(h0);
        const float l1 = v1 - __bfloat162float(h1);
        smu[SM_XLO + i] = (uint32_t)__bfloat16_as_ushort(__float2bfloat16_rn(l0)) |
                          ((uint32_t)__bfloat16_as_ushort(__float2bfloat16_rn(l1)) << 16);
    }

    if (wid < 8) {
        // =================== MMA role: co 0..111 ===================
        const int lq    = lane >> 2;
        const int lr4   = lane & 3;
        const int warpM = wid >> 1;     // 0..3
        const int warpN = wid & 1;      // 0..1

        float acc[2][7][4];
#pragma unroll
        for (int mt = 0; mt < 2; mt++)
#pragma unroll
            for (int n = 0; n < 7; n++)
#pragma unroll
                for (int k = 0; k < 4; k++) acc[mt][n][k] = 0.0f;

        const uint32_t* srcM = g_wBm + (size_t)g * 9 * 3584;

        for (int tap = 0; tap < 9; ++tap) {
            __syncthreads();
            for (int i = tid; i < 3584; i += 256)
                smu[SM_BM + (i / 112) * 120 + (i % 112)] = srcM[tap * 3584 + i];
            __syncthreads();

            const int kh = tap / 3;
            const int kw = tap - kh * 3;
            const int abase = (warpM + kh) * 36 + kw + lq;
            const uint32_t* bp0 = smu + SM_BM + lr4 * 120 + warpN * 56 + lq;

#pragma unroll
            for (int kc = 0; kc < 4; ++kc) {
                uint32_t b0[7], b1[7];
                const uint32_t* bp = bp0 + kc * 8 * 120;
#pragma unroll
                for (int n = 0; n < 7; ++n) {
                    b0[n] = bp[n * 8];
                    b1[n] = bp[4 * 120 + n * 8];
                }
#pragma unroll
                for (int pass = 0; pass < 2; ++pass) {
                    const uint32_t* sxp = smu + (pass ? SM_XLO : SM_XHI)
                                          + (kc * 8 + lr4) * 216 + abase;
                    uint32_t A[2][4];
#pragma unroll
                    for (int mt = 0; mt < 2; ++mt) {
                        A[mt][0] = sxp[mt * 16];
                        A[mt][1] = sxp[mt * 16 + 8];
                        A[mt][2] = sxp[4 * 216 + mt * 16];
                        A[mt][3] = sxp[4 * 216 + mt * 16 + 8];
                    }
#pragma unroll
                    for (int n = 0; n < 7; ++n)
#pragma unroll
                        for (int mt = 0; mt < 2; ++mt)
                            mma_bf16(acc[mt][n][0], acc[mt][n][1], acc[mt][n][2], acc[mt][n][3],
                                     A[mt][0], A[mt][1], A[mt][2], A[mt][3],
                                     b0[n], b1[n]);
                }
            }
        }

        // epilogue: D -> g_psum
        const int rimg = r0 + warpM;
#pragma unroll
        for (int mt = 0; mt < 2; ++mt) {
            const int px0 = rimg * 32 + mt * 16 + lq;
#pragma unroll
            for (int n = 0; n < 7; ++n) {
                const int co = g * 256 + warpN * 56 + n * 8 + lr4 * 2;
                float* base = g_psum + ((size_t)(b * 1024 + co)) * 1024;
                base[px0]            = acc[mt][n][0];
                base[1024 + px0]     = acc[mt][n][1];
                base[px0 + 8]        = acc[mt][n][2];
                base[1024 + px0 + 8] = acc[mt][n][3];
            }
        }
    } else {
        // =================== FFMA role: co 112..255 ===================
        const int f   = tid - 256;      // 0..255
        const int ct  = f >> 4;         // 0..15 -> 9 co each
        const int pt2 = f & 15;
        const int prow = pt2 >> 2;      // 0..3
        const int c0   = (pt2 & 3) * 8; // 0,8,16,24

        unsigned long long acc[36];
#pragma unroll
        for (int i = 0; i < 36; i++) acc[i] = 0ull;

        const unsigned long long* srcF = g_wBf + (size_t)g * 9 * 10240;

        for (int tap = 0; tap < 9; ++tap) {
            __syncthreads();
            for (int i = f; i < 10240; i += 256)
                smw[i] = srcF[(size_t)tap * 10240 + i];
            __syncthreads();

            const int kh = tap / 3;
            const int kw = tap - kh * 3;
            const float* xp = sm + SM_XF32 + (prow + kh) * 36 + c0 + kw;

#pragma unroll 2
            for (int ci = 0; ci < 64; ++ci) {
                const float* xq = xp + ci * 216;
                const float v0 = xq[0], v1 = xq[1], v2 = xq[2], v3 = xq[3];
                const float v4 = xq[4], v5 = xq[5], v6 = xq[6], v7 = xq[7];
                const unsigned long long p0 = packab(v0, v1);
                const unsigned long long p1 = packab(v2, v3);
                const unsigned long long p2 = packab(v4, v5);
                const unsigned long long p3 = packab(v6, v7);

                const unsigned long long* wq = smw + (ci * 16 + ct) * 10;
                const ulonglong2 wA = *reinterpret_cast<const ulonglong2*>(wq);
                const ulonglong2 wB = *reinterpret_cast<const ulonglong2*>(wq + 2);
                const ulonglong2 wC = *reinterpret_cast<const ulonglong2*>(wq + 4);
                const ulonglong2 wD = *reinterpret_cast<const ulonglong2*>(wq + 6);
                const unsigned long long w8 = wq[8];

#define FSTEP(WD, J)                                   \
                acc[(J)*4+0] = ffma2(p0, (WD), acc[(J)*4+0]); \
                acc[(J)*4+1] = ffma2(p1, (WD), acc[(J)*4+1]); \
                acc[(J)*4+2] = ffma2(p2, (WD), acc[(J)*4+2]); \
                acc[(J)*4+3] = ffma2(p3, (WD), acc[(J)*4+3]);
                FSTEP(wA.x, 0) FSTEP(wA.y, 1)
                FSTEP(wB.x, 2) FSTEP(wB.y, 3)
                FSTEP(wC.x, 4) FSTEP(wC.y, 5)
                FSTEP(wD.x, 6) FSTEP(wD.y, 7)
                FSTEP(w8,   8)
#undef FSTEP
            }
        }

        // epilogue: 9 co x 8 px per thread
        const int rimg = r0 + prow;
#pragma unroll
        for (int j = 0; j < 9; ++j) {
            const int chan = g * 256 + 112 + ct * 9 + j;
            float* base = g_psum + ((size_t)(b * 1024 + chan)) * 1024 + rimg * 32 + c0;
            float2 q0 = *reinterpret_cast<float2*>(&acc[j * 4 + 0]);
            float2 q1 = *reinterpret_cast<float2*>(&acc[j * 4 + 1]);
            float2 q2 = *reinterpret_cast<float2*>(&acc[j * 4 + 2]);
            float2 q3 = *reinterpret_cast<float2*>(&acc[j * 4 + 3]);
            *reinterpret_cast<float4*>(base)     = make_float4(q0.x, q0.y, q1.x, q1.y);
            *reinterpret_cast<float4*>(base + 4) = make_float4(q2.x, q2.y, q3.x, q3.y);
        }
    }
}

// ---------------------------------------------------------------------------
// K2: per-channel stats over S -> scale/bias (alpha + eps folded).
// ---------------------------------------------------------------------------
__global__ void k_stats(const float* __restrict__ gamma,
                        const float* __restrict__ beta) {
    const int ch = blockIdx.x;     // 1024
    const int t  = threadIdx.x;    // 256
    __shared__ float rs[256], rq[256];
    float s = 0.0f, q = 0.0f;
    for (int i = t; i < 32768; i += 256) {
        const int bb = i >> 10;
        const int px = i & 1023;
        const float v = g_psum[((size_t)(bb * 1024 + ch)) * 1024 + px];
        s += v; q += v * v;
    }
    rs[t] = s; rq[t] = q;
    __syncthreads();
    for (int off = 128; off; off >>= 1) {
        if (t < off) { rs[t] += rs[t + off]; rq[t] += rq[t + off]; }
        __syncthreads();
    }
    if (t == 0) {
        const float mean = rs[0] * (1.0f / 32768.0f);
        const float var  = rq[0] * (1.0f / 32768.0f) - mean * mean;
        const float a    = g_alpha[ch & 255];
        const float inv  = gamma[ch] / sqrtf(a * a * var + 1e-5f);
        const float sc   = a * inv;
        g_scale[ch] = sc;
        g_bias[ch]  = beta[ch] - mean * sc;
    }
}

// ---------------------------------------------------------------------------
// K3: threshold + merge + qrelu LUT; flag near-threshold pixels.
// ---------------------------------------------------------------------------
__global__ void k_out(float* __restrict__ out) {
    const int idx = blockIdx.x * 256 + threadIdx.x;
    const int b    = idx >> 16;
    const int qb   = idx & 65535;
    const int co   = qb >> 8;
    const int pix4 = qb & 255;

    const float4* pb = reinterpret_cast<const float4*>(g_psum);
    int c0 = 0, c1 = 0, c2 = 0, c3 = 0;
    bool f0 = false, f1 = false, f2 = false, f3 = false;
#pragma unroll
    for (int g = 0; g < 4; g++) {
        const int chan = g * 256 + co;
        const float4 p = pb[(size_t)(b * 1024 + chan) * 256 + pix4];
        const float sc = g_scale[chan];
        const float bi = g_bias[chan];
        const float band = fabsf(sc) * TAU;
        const float m0 = p.x * sc + bi;
        const float m1 = p.y * sc + bi;
        const float m2 = p.z * sc + bi;
        const float m3 = p.w * sc + bi;
        c0 += (m0 >= 0.0f); f0 |= (fabsf(m0) < band);
        c1 += (m1 >= 0.0f); f1 |= (fabsf(m1) < band);
        c2 += (m2 >= 0.0f); f2 |= (fabsf(m2) < band);
        c3 += (m3 >= 0.0f); f3 |= (fabsf(m3) < band);
    }
    const float Q3 = (8.0f / 15.0f) * 4.0f;
    float4 o;
    o.x = (c0 == 4) ? 4.0f : ((c0 == 3) ? Q3 : 0.0f);
    o.y = (c1 == 4) ? 4.0f : ((c1 == 3) ? Q3 : 0.0f);
    o.z = (c2 == 4) ? 4.0f : ((c2 == 3) ? Q3 : 0.0f);
    o.w = (c3 == 4) ? 4.0f : ((c3 == 3) ? Q3 : 0.0f);
    reinterpret_cast<float4*>(out)[idx] = o;

    if (f0 | f1 | f2 | f3) {
        const int base = (b << 18) | (co << 10) | (pix4 << 2);
#pragma unroll
        for (int comp = 0; comp < 4; ++comp) {
            const bool f = (comp == 0) ? f0 : (comp == 1) ? f1 : (comp == 2) ? f2 : f3;
            if (f) {
                const int slot = atomicAdd(&g_cnt, 1);
                if (slot < CAP) g_list[slot] = base | comp;
            }
        }
    }
}

// ---------------------------------------------------------------------------
// K4: exact (double) recompute of flagged decisions; rewrite out. Idempotent.
// ---------------------------------------------------------------------------
__global__ void k_fix(const float* __restrict__ x, const float* __restrict__ w,
                      float* __restrict__ out) {
    const int n = (g_cnt < CAP) ? g_cnt : CAP;
    for (int i = blockIdx.x * blockDim.x + threadIdx.x; i < n;
         i += gridDim.x * blockDim.x) {
        const int item = g_list[i];
        const int b   = item >> 18;
        const int co  = (item >> 10) & 255;
        const int pix = item & 1023;
        const int h = pix >> 5, wp = pix & 31;
        int c = 0;
#pragma unroll 1
        for (int g = 0; g < 4; g++) {
            const int chan = g * 256 + co;
            const float sc = g_scale[chan];
            const float bi = g_bias[chan];
            const float S  = g_psum[((size_t)(b * 1024 + chan)) * 1024 + pix];
            const float m  = S * sc + bi;
            int bit;
            if (fabsf(m) < fabsf(sc) * TAU) {
                double s = 0.0;
                const float* xb = x + ((size_t)(b * 256 + g * 64)) * 1024;
                const float* wb = w + (size_t)co * 2304 + (size_t)g * 64 * 9;
                for (int cig = 0; cig < 64; cig++) {
                    const float* xc = xb + cig * 1024;
                    const float* wc = wb + cig * 9;
#pragma unroll
                    for (int kh = 0; kh < 3; kh++) {
                        const int hh = h + kh - 1;
                        if ((unsigned)hh >= 32u) continue;
#pragma unroll
                        for (int kw = 0; kw < 3; kw++) {
                            const int ww = wp + kw - 1;
                            if ((unsigned)ww >= 32u) continue;
                            const float xv = __ldg(xc + hh * 32 + ww);
                            s += (__ldg(wc + kh * 3 + kw) >= 0.0f) ? (double)xv
                                                                   : -(double)xv;
                        }
                    }
                }
                const double md = s * (double)sc + (double)bi;
                bit = (md >= 0.0);
            } else {
                bit = (m >= 0.0f);
            }
            c += bit;
        }
        const float Q3 = (8.0f / 15.0f) * 4.0f;
        out[((size_t)(b * 256 + co)) * 1024 + pix] =
            (c == 4) ? 4.0f : ((c == 3) ? Q3 : 0.0f);
    }
}

// ---------------------------------------------------------------------------
extern "C" void kernel_launch(void* const* d_in, const int* in_sizes, int n_in,
                              void* d_out, int out_size) {
    const float* x      = (const float*)d_in[0];
    const float* weight = (const float*)d_in[1];
    const float* gamma  = (const float*)d_in[2];
    const float* beta   = (const float*)d_in[3];
    float* out = (float*)d_out;

    cudaFuncSetAttribute(k_conv, cudaFuncAttributeMaxDynamicSharedMemorySize, SM_BYTES);

    k_prep<<<256, 256>>>(weight);
    k_conv<<<dim3(8, 4, 32), 512, SM_BYTES>>>(x);
    k_stats<<<1024, 256>>>(gamma, beta);
    k_out<<<8192, 256>>>(out);
    k_fix<<<512, 128>>>(x, weight, out);
}